// round 6
// baseline (speedup 1.0000x reference)
#include <cuda_runtime.h>
#include <math.h>

#define NP     100
#define BATCH  256
#define FD     256
#define NOUT   30

__device__ float        g_m[3][BATCH][NOUT];
__device__ unsigned int g_cnt[BATCH];

__device__ __forceinline__ float wred(float v) {
    #pragma unroll
    for (int o = 16; o; o >>= 1) v += __shfl_xor_sync(0xffffffffu, v, o);
    return v;
}

// amplitude index: bits 0..1 = reg m, bits 2..6 = lane, bits 7..9 = warp (w = t8>>5)

// ---------------- 1q gate, bit B in 0..6 ----------------
template<int B>
__device__ __forceinline__ void apply1q(float* vr, float* vi, int lane,
    float U00r, float U00i, float U01r, float U01i,
    float U10r, float U10i, float U11r, float U11i)
{
    if constexpr (B < 2) {
        #pragma unroll
        for (int q = 0; q < 2; ++q) {
            const int m0 = ((q >> B) << (B + 1)) | (q & ((1 << B) - 1));
            const int m1 = m0 | (1 << B);
            float a0r = vr[m0], a0i = vi[m0], a1r = vr[m1], a1i = vi[m1];
            vr[m0] = U00r*a0r - U00i*a0i + U01r*a1r - U01i*a1i;
            vi[m0] = U00r*a0i + U00i*a0r + U01r*a1i + U01i*a1r;
            vr[m1] = U10r*a0r - U10i*a0i + U11r*a1r - U11i*a1i;
            vi[m1] = U10r*a0i + U10i*a0r + U11r*a1i + U11i*a1r;
        }
    } else {
        constexpr int lm = 1 << (B - 2);
        const bool r = (lane & lm) != 0;
        float cmr = r ? U11r : U00r, cmi = r ? U11i : U00i;
        float cpr = r ? U10r : U01r, cpi = r ? U10i : U01i;
        #pragma unroll
        for (int m = 0; m < 4; ++m) {
            float pr = __shfl_xor_sync(0xffffffffu, vr[m], lm);
            float pi = __shfl_xor_sync(0xffffffffu, vi[m], lm);
            float mr = vr[m], mi = vi[m];
            vr[m] = cmr*mr - cmi*mi + cpr*pr - cpi*pi;
            vi[m] = cmr*mi + cmi*mr + cpr*pi + cpi*pr;
        }
    }
}

// 1q gate on warp bit, WM = warp xor mask (1,2,4 for bits 7,8,9)
template<int WM>
__device__ __forceinline__ void apply1qW(float* vr, float* vi, int t8, int w,
    float2 (*ex)[256],
    float U00r, float U00i, float U01r, float U01i,
    float U10r, float U10i, float U11r, float U11i)
{
    const bool hi = (w & WM) != 0;
    float cmr = hi ? U11r : U00r, cmi = hi ? U11i : U00i;
    float cpr = hi ? U10r : U01r, cpi = hi ? U10i : U01i;
    __syncthreads();
    #pragma unroll
    for (int m = 0; m < 4; ++m) ex[m][t8] = make_float2(vr[m], vi[m]);
    __syncthreads();
    const int p = t8 ^ (WM << 5);
    #pragma unroll
    for (int m = 0; m < 4; ++m) {
        float2 pv = ex[m][p];
        float mr = vr[m], mi = vi[m];
        vr[m] = cmr*mr - cmi*mi + cpr*pv.x - cpi*pv.y;
        vi[m] = cmr*mi + cmi*mr + cpr*pv.y + cpi*pv.x;
    }
}

// ---------------- controlled-RX, target bit BT <= 6, control BC in 0..9 ----------------
template<int BC, int BT>
__device__ __forceinline__ void applycrx(float* vr, float* vi, int lane, int w, float cg, float sg)
{
    bool act = true;
    if constexpr (BC >= 7)      act = (w & (1 << (BC - 7))) != 0;
    else if constexpr (BC >= 2) act = (lane & (1 << (BC - 2))) != 0;

    if constexpr (BT < 2) {
        if constexpr (BC < 2) {
            // both reg bits: single pair (ctrl=1, tgt 0->1)
            constexpr int m0 = (1 << BC);
            constexpr int m1 = m0 | (1 << BT);
            float a0r = vr[m0], a0i = vi[m0], a1r = vr[m1], a1i = vi[m1];
            vr[m0] = cg*a0r + sg*a1i; vi[m0] = cg*a0i - sg*a1r;
            vr[m1] = cg*a1r + sg*a0i; vi[m1] = cg*a1i - sg*a0r;
        } else {
            if (act) {
                #pragma unroll
                for (int q = 0; q < 2; ++q) {
                    const int m0 = ((q >> BT) << (BT + 1)) | (q & ((1 << BT) - 1));
                    const int m1 = m0 | (1 << BT);
                    float a0r = vr[m0], a0i = vi[m0], a1r = vr[m1], a1i = vi[m1];
                    vr[m0] = cg*a0r + sg*a1i; vi[m0] = cg*a0i - sg*a1r;
                    vr[m1] = cg*a1r + sg*a0i; vi[m1] = cg*a1i - sg*a0r;
                }
            }
        }
    } else {
        constexpr int lm = 1 << (BT - 2);
        if constexpr (BC < 2) {
            #pragma unroll
            for (int m = 0; m < 4; ++m)
                if (m & (1 << BC)) {
                    float pr = __shfl_xor_sync(0xffffffffu, vr[m], lm);
                    float pi = __shfl_xor_sync(0xffffffffu, vi[m], lm);
                    float mr = vr[m], mi = vi[m];
                    vr[m] = cg*mr + sg*pi; vi[m] = cg*mi - sg*pr;
                }
        } else if constexpr (BC >= 7) {
            if (act) {   // warp-uniform
                #pragma unroll
                for (int m = 0; m < 4; ++m) {
                    float pr = __shfl_xor_sync(0xffffffffu, vr[m], lm);
                    float pi = __shfl_xor_sync(0xffffffffu, vi[m], lm);
                    float mr = vr[m], mi = vi[m];
                    vr[m] = cg*mr + sg*pi; vi[m] = cg*mi - sg*pr;
                }
            }
        } else {
            #pragma unroll
            for (int m = 0; m < 4; ++m) {
                float pr = __shfl_xor_sync(0xffffffffu, vr[m], lm);
                float pi = __shfl_xor_sync(0xffffffffu, vi[m], lm);
                float mr = vr[m], mi = vi[m];
                float nr = cg*mr + sg*pi, ni = cg*mi - sg*pr;
                vr[m] = act ? nr : mr; vi[m] = act ? ni : mi;
            }
        }
    }
}

// controlled-RX with target = warp bit (WM = xor mask); RM = reg mask filter (0 = all regs)
template<int WM, int RM>
__device__ __forceinline__ void applycrxW(float* vr, float* vi, int t8,
    float2 (*ex)[256], float cg, float sg, bool act)
{
    __syncthreads();
    if (act) {
        #pragma unroll
        for (int m = 0; m < 4; ++m) {
            if constexpr (RM != 0) { if (!(m & RM)) continue; }
            ex[m][t8] = make_float2(vr[m], vi[m]);
        }
    }
    __syncthreads();
    if (act) {
        const int p = t8 ^ (WM << 5);
        #pragma unroll
        for (int m = 0; m < 4; ++m) {
            if constexpr (RM != 0) { if (!(m & RM)) continue; }
            float2 pv = ex[m][p];
            float mr = vr[m], mi = vi[m];
            vr[m] = cg*mr + sg*pv.y; vi[m] = cg*mi - sg*pv.x;
        }
    }
}

// ---------------- measurements (per-warp partials) ----------------
template<int B>   // B 0..6
__device__ __forceinline__ void measure(const float* vr, const float* vi, int lane,
                                        float& X, float& Y, float& Z)
{
    float zr = 0.f, zi = 0.f, zd = 0.f;
    if constexpr (B < 2) {
        #pragma unroll
        for (int q = 0; q < 2; ++q) {
            const int m0 = ((q >> B) << (B + 1)) | (q & ((1 << B) - 1));
            const int m1 = m0 | (1 << B);
            zr += vr[m0]*vr[m1] + vi[m0]*vi[m1];
            zi += vr[m0]*vi[m1] - vi[m0]*vr[m1];
            zd += vr[m0]*vr[m0] + vi[m0]*vi[m0] - vr[m1]*vr[m1] - vi[m1]*vi[m1];
        }
        X = 2.f * wred(zr); Y = 2.f * wred(zi); Z = wred(zd);
    } else {
        constexpr int lm = 1 << (B - 2);
        const float sgn = (lane & lm) ? -1.f : 1.f;
        #pragma unroll
        for (int m = 0; m < 4; ++m) {
            float pr = __shfl_xor_sync(0xffffffffu, vr[m], lm);
            float pi = __shfl_xor_sync(0xffffffffu, vi[m], lm);
            float mr = vr[m], mi = vi[m];
            zr += mr*pr + mi*pi;
            zi += mr*pi - mi*pr;
            zd += mr*mr + mi*mi;
        }
        X = wred(zr); Y = wred(zi * sgn); Z = wred(zd * sgn);
    }
}

template<int WM>
__device__ __forceinline__ void measureW(const float* vr, const float* vi, int t8, int w,
    float2 (*ex)[256], float& X, float& Y, float& Z)
{
    __syncthreads();
    #pragma unroll
    for (int m = 0; m < 4; ++m) ex[m][t8] = make_float2(vr[m], vi[m]);
    __syncthreads();
    const int p = t8 ^ (WM << 5);
    const float sgn = (w & WM) ? -1.f : 1.f;
    float zr = 0.f, zi = 0.f, zd = 0.f;
    #pragma unroll
    for (int m = 0; m < 4; ++m) {
        float2 pv = ex[m][p];
        float mr = vr[m], mi = vi[m];
        zr += mr*pv.x + mi*pv.y;
        zi += mr*pv.y - mi*pv.x;
        zd += mr*mr + mi*mi;
    }
    X = wred(zr); Y = wred(zi * sgn); Z = wred(zd * sgn);
}

// ---------------- kernel: one block per (batch, branch), 256 threads = 8 warps ----------------
__global__ void __launch_bounds__(256, 4) qsb_fused(
    const float* __restrict__ x,
    const float* __restrict__ W1, const float* __restrict__ b1, const float* __restrict__ base1,
    const float* __restrict__ W2, const float* __restrict__ b2, const float* __restrict__ base2,
    const float* __restrict__ W3, const float* __restrict__ b3, const float* __restrict__ base3,
    const float* __restrict__ ar_, const float* __restrict__ ai_,
    const float* __restrict__ br_, const float* __restrict__ bi_,
    const float* __restrict__ gr_, const float* __restrict__ gi_,
    float* __restrict__ out)
{
    const int bt   = blockIdx.x & 255;
    const int br   = blockIdx.x >> 8;
    const int t8   = threadIdx.x;
    const int lane = t8 & 31;
    const int w    = t8 >> 5;

    const float* __restrict__ W  = (br == 0) ? W1 : (br == 1) ? W2 : W3;
    const float* __restrict__ bb = (br == 0) ? b1 : (br == 1) ? b2 : b3;
    const float* __restrict__ bs = (br == 0) ? base1 : (br == 1) ? base2 : base3;

    __shared__ __align__(16) float xs[FD];
    __shared__ float2 scs[NP];            // (cos, sin) of half-angle
    __shared__ float  pp[2 * NP];
    __shared__ float2 ex[4][256];
    __shared__ float  mpart[8][NOUT];
    __shared__ int    sIsLast;

    // ---- stage x row ----
    xs[t8] = x[bt * FD + t8];
    __syncthreads();

    // ---- params: 200 threads compute half-dots, 100 threads finish ----
    if (t8 < 2 * NP) {
        const int j = t8 >> 1, hf = t8 & 1;
        const float4* __restrict__ w4 = (const float4*)(W + j * FD) + hf * 32;
        const float4* __restrict__ x4 = (const float4*)xs + hf * 32;
        float a0 = 0.f, a1 = 0.f;
        #pragma unroll
        for (int k = 0; k < 32; k += 2) {
            float4 wv0 = w4[k],   xv0 = x4[k];
            float4 wv1 = w4[k+1], xv1 = x4[k+1];
            a0 = fmaf(wv0.x, xv0.x, fmaf(wv0.y, xv0.y, fmaf(wv0.z, xv0.z, fmaf(wv0.w, xv0.w, a0))));
            a1 = fmaf(wv1.x, xv1.x, fmaf(wv1.y, xv1.y, fmaf(wv1.z, xv1.z, fmaf(wv1.w, xv1.w, a1))));
        }
        pp[t8] = a0 + a1;
    }
    __syncthreads();
    if (t8 < NP) {
        float t = pp[2 * t8] + pp[2 * t8 + 1] + bb[t8] + bs[t8];
        float half = 3.14159265358979f / (1.0f + __expf(-t));   // (sigmoid*2pi)/2
        float cc2, sn2;
        __sincosf(half, &sn2, &cc2);
        scs[t8] = make_float2(cc2, sn2);
    }
    __syncthreads();

    // ---- circuit ----
    float vr[4], vi[4];
    #pragma unroll
    for (int m = 0; m < 4; ++m) { vr[m] = 0.f; vi[m] = 0.f; }
    if (t8 == 0) vr[0] = 1.0f;

    int idx = 0;

    #define UCOEF \
        float2 p1 = scs[idx], p2 = scs[idx+1], p3 = scs[idx+2]; idx += 3; \
        float c1 = p1.x, s1 = p1.y, c2 = p2.x, s2 = p2.y, c3 = p3.x, s3 = p3.y; \
        float A00r =  c2*c1, A00i =  s2*s1; \
        float A01r = -s2*c1, A01i = -c2*s1; \
        float A10r =  s2*c1, A10i = -c2*s1; \
        float A11r =  c2*c1, A11i = -s2*s1; \
        float U00r = c3*A00r + s3*A00i, U00i = c3*A00i - s3*A00r; \
        float U01r = c3*A01r + s3*A01i, U01i = c3*A01i - s3*A01r; \
        float U10r = c3*A10r - s3*A10i, U10i = c3*A10i + s3*A10r; \
        float U11r = c3*A11r - s3*A11i, U11i = c3*A11i + s3*A11r;

    #define FUSED(B) { UCOEF \
        apply1q<B>(vr, vi, lane, U00r,U00i,U01r,U01i,U10r,U10i,U11r,U11i); }
    #define FUSEDW(WM) { UCOEF \
        apply1qW<WM>(vr, vi, t8, w, ex, U00r,U00i,U01r,U01i,U10r,U10i,U11r,U11i); }
    #define CRX(BC,BT) { float2 p = scs[idx]; idx++; \
        applycrx<BC,BT>(vr, vi, lane, w, p.x, p.y); }
    #define CRXW(WM,RM,ACT) { float2 p = scs[idx]; idx++; \
        applycrxW<WM,RM>(vr, vi, t8, ex, p.x, p.y, (ACT)); }

    #pragma unroll 1
    for (int layer = 0; layer < 2; ++layer) {
        // 1q triples, wires 0..9 -> bits 9..0
        FUSEDW(4) FUSEDW(2) FUSEDW(1)
        FUSED(6) FUSED(5) FUSED(4) FUSED(3) FUSED(2)
        FUSED(1) FUSED(0)
        // forward ring (bit space): (9,8)(8,7)(7,6)(6,5)(5,4)(4,3)(3,2)(2,1)(1,0)(0,9)
        CRXW(2, 0, (w & 4) != 0)
        CRXW(1, 0, (w & 2) != 0)
        CRX(7,6) CRX(6,5) CRX(5,4) CRX(4,3) CRX(3,2)
        CRX(2,1) CRX(1,0)
        CRXW(4, 1, true)
        // backward ring: (0,1)(1,2)(2,3)(3,4)(4,5)(5,6)(6,7)(7,8)(8,9)(9,0)
        CRX(0,1) CRX(1,2) CRX(2,3) CRX(3,4) CRX(4,5) CRX(5,6)
        CRXW(1, 0, (lane & 16) != 0)
        CRXW(2, 0, (w & 1) != 0)
        CRXW(4, 0, (w & 2) != 0)
        CRX(9,0)
    }

    // ---- measurements (wire v -> bit 9-v) ----
    {
        float X, Y, Z;
        measureW<4>(vr, vi, t8, w, ex, X, Y, Z);
        if (lane == 0) { mpart[w][0] = X; mpart[w][10] = Y; mpart[w][20] = Z; }
        __syncthreads();
        if (t8 < NOUT) {
            float s = 0.f;
            #pragma unroll
            for (int k = 0; k < 8; ++k) s += mpart[k][t8];
            pp[t8] = s;   // reuse pp as accumulation of final expvals
        }
    }
    {
        float X, Y, Z;
        measureW<2>(vr, vi, t8, w, ex, X, Y, Z);
        if (lane == 0) { mpart[w][1] = X; mpart[w][11] = Y; mpart[w][21] = Z; }
    }
    {
        float X, Y, Z;
        measureW<1>(vr, vi, t8, w, ex, X, Y, Z);
        if (lane == 0) { mpart[w][2] = X; mpart[w][12] = Y; mpart[w][22] = Z; }
    }
    #define MEAS(v) { float X, Y, Z; measure<9-(v)>(vr, vi, lane, X, Y, Z); \
        if (lane == 0) { mpart[w][v] = X; mpart[w][10+(v)] = Y; mpart[w][20+(v)] = Z; } }
    MEAS(3) MEAS(4) MEAS(5) MEAS(6) MEAS(7) MEAS(8) MEAS(9)
    __syncthreads();

    // ---- reduce partials, publish, last-block combine ----
    if (t8 < NOUT) {
        float s = 0.f;
        if (t8 == 0 || t8 == 10 || t8 == 20) {
            s = pp[t8];   // wire 0 already reduced (ex buffer was reused after)
        } else {
            #pragma unroll
            for (int k = 0; k < 8; ++k) s += mpart[k][t8];
        }
        g_m[br][bt][t8] = s;
        __threadfence();
    }
    __syncthreads();
    if (t8 == 0) {
        unsigned int old = atomicAdd(&g_cnt[bt], 1u);
        sIsLast = (old == 2u);
    }
    __syncthreads();
    if (sIsLast) {
        if (t8 < NOUT) {
            __threadfence();
            float m1 = g_m[0][bt][t8];
            float m2 = g_m[1][bt][t8];
            float m3 = g_m[2][bt][t8];
            float ar = ar_[0], ai = ai_[0];
            float brv = br_[0], bi = bi_[0];
            float gr = gr_[0], gi = gi_[0];
            float norm = sqrtf(ar*ar + ai*ai + brv*brv + bi*bi + gr*gr + gi*gi + 1e-9f);
            float re = (ar * m1 + brv * m2 + gr * m3) / norm;
            float im = (ai * m1 + bi * m2 + gi * m3) / norm;
            out[bt * NOUT + t8] = sqrtf(re * re + im * im);
        }
        if (t8 == 0) g_cnt[bt] = 0u;   // reset for next graph replay
    }
}

extern "C" void kernel_launch(void* const* d_in, const int* in_sizes, int n_in,
                              void* d_out, int out_size)
{
    // d_in order: x, W1, b1, W2, b2, W3, b3, base1, base2, base3, ar, ai, br, bi, gr, gi
    qsb_fused<<<3 * BATCH, 256>>>(
        (const float*)d_in[0],
        (const float*)d_in[1], (const float*)d_in[2], (const float*)d_in[7],
        (const float*)d_in[3], (const float*)d_in[4], (const float*)d_in[8],
        (const float*)d_in[5], (const float*)d_in[6], (const float*)d_in[9],
        (const float*)d_in[10], (const float*)d_in[11],
        (const float*)d_in[12], (const float*)d_in[13],
        (const float*)d_in[14], (const float*)d_in[15],
        (float*)d_out);
}

// round 7
// speedup vs baseline: 1.1090x; 1.1090x over previous
#include <cuda_runtime.h>
#include <math.h>

#define NP     100
#define BATCH  256
#define FD     256
#define NOUT   30

__device__ float        g_m[3][BATCH][NOUT];
__device__ unsigned int g_cnt[BATCH];

__device__ __forceinline__ float wred(float v) {
    #pragma unroll
    for (int o = 16; o; o >>= 1) v += __shfl_xor_sync(0xffffffffu, v, o);
    return v;
}

// amplitude index: bits 0..2 = reg m, bits 3..7 = lane, bits 8..9 = warp (w = t7>>5)

// ---------------- 1q gate, bit B in 0..7 ----------------
template<int B>
__device__ __forceinline__ void apply1q(float* vr, float* vi, int lane,
    float U00r, float U00i, float U01r, float U01i,
    float U10r, float U10i, float U11r, float U11i)
{
    if constexpr (B < 3) {
        constexpr int st = 1 << B;
        #pragma unroll
        for (int q = 0; q < 4; ++q) {
            const int m0 = ((q >> B) << (B + 1)) | (q & (st - 1));
            const int m1 = m0 | st;
            float a0r = vr[m0], a0i = vi[m0], a1r = vr[m1], a1i = vi[m1];
            vr[m0] = U00r*a0r - U00i*a0i + U01r*a1r - U01i*a1i;
            vi[m0] = U00r*a0i + U00i*a0r + U01r*a1i + U01i*a1r;
            vr[m1] = U10r*a0r - U10i*a0i + U11r*a1r - U11i*a1i;
            vi[m1] = U10r*a0i + U10i*a0r + U11r*a1i + U11i*a1r;
        }
    } else {
        constexpr int lm = 1 << (B - 3);
        const bool r = (lane & lm) != 0;
        float cmr = r ? U11r : U00r, cmi = r ? U11i : U00i;
        float cpr = r ? U10r : U01r, cpi = r ? U10i : U01i;
        #pragma unroll
        for (int m = 0; m < 8; ++m) {
            float pr = __shfl_xor_sync(0xffffffffu, vr[m], lm);
            float pi = __shfl_xor_sync(0xffffffffu, vi[m], lm);
            float mr = vr[m], mi = vi[m];
            vr[m] = cmr*mr - cmi*mi + cpr*pr - cpi*pi;
            vi[m] = cmr*mi + cmi*mr + cpr*pi + cpi*pr;
        }
    }
}

// 1q gate on warp bit (WM = 1 -> bit8, WM = 2 -> bit9), cross-warp float2 exchange
template<int WM>
__device__ __forceinline__ void apply1qW(float* vr, float* vi, int t7, int w,
    float2 (*ex)[128],
    float U00r, float U00i, float U01r, float U01i,
    float U10r, float U10i, float U11r, float U11i)
{
    const bool hi = (w & WM) != 0;
    float cmr = hi ? U11r : U00r, cmi = hi ? U11i : U00i;
    float cpr = hi ? U10r : U01r, cpi = hi ? U10i : U01i;
    __syncthreads();
    #pragma unroll
    for (int m = 0; m < 8; ++m) ex[m][t7] = make_float2(vr[m], vi[m]);
    __syncthreads();
    const int p = t7 ^ (WM << 5);
    #pragma unroll
    for (int m = 0; m < 8; ++m) {
        float2 pv = ex[m][p];
        float mr = vr[m], mi = vi[m];
        vr[m] = cmr*mr - cmi*mi + cpr*pv.x - cpi*pv.y;
        vi[m] = cmr*mi + cmi*mr + cpr*pv.y + cpi*pv.x;
    }
}

// ---------------- controlled-RX, target bit BT <= 7, control BC in 0..9 ----------------
template<int BC, int BT>
__device__ __forceinline__ void applycrx(float* vr, float* vi, int lane, int w, float cg, float sg)
{
    bool act = true;
    if constexpr (BC >= 8)      act = (w & (1 << (BC - 8))) != 0;
    else if constexpr (BC >= 3) act = (lane & (1 << (BC - 3))) != 0;

    if constexpr (BT < 3) {
        constexpr int tm = 1 << BT;
        if constexpr (BC < 3) {
            #pragma unroll
            for (int m0 = 0; m0 < 8; ++m0)
                if ((m0 & (1 << BC)) && !(m0 & tm)) {
                    const int m1 = m0 | tm;
                    float a0r = vr[m0], a0i = vi[m0], a1r = vr[m1], a1i = vi[m1];
                    vr[m0] = cg*a0r + sg*a1i; vi[m0] = cg*a0i - sg*a1r;
                    vr[m1] = cg*a1r + sg*a0i; vi[m1] = cg*a1i - sg*a0r;
                }
        } else {
            if (act) {
                #pragma unroll
                for (int q = 0; q < 4; ++q) {
                    const int m0 = ((q >> BT) << (BT + 1)) | (q & (tm - 1));
                    const int m1 = m0 | tm;
                    float a0r = vr[m0], a0i = vi[m0], a1r = vr[m1], a1i = vi[m1];
                    vr[m0] = cg*a0r + sg*a1i; vi[m0] = cg*a0i - sg*a1r;
                    vr[m1] = cg*a1r + sg*a0i; vi[m1] = cg*a1i - sg*a0r;
                }
            }
        }
    } else {
        constexpr int lm = 1 << (BT - 3);
        if constexpr (BC < 3) {
            #pragma unroll
            for (int m = 0; m < 8; ++m)
                if (m & (1 << BC)) {
                    float pr = __shfl_xor_sync(0xffffffffu, vr[m], lm);
                    float pi = __shfl_xor_sync(0xffffffffu, vi[m], lm);
                    float mr = vr[m], mi = vi[m];
                    vr[m] = cg*mr + sg*pi; vi[m] = cg*mi - sg*pr;
                }
        } else if constexpr (BC >= 8) {
            if (act) {   // warp-uniform
                #pragma unroll
                for (int m = 0; m < 8; ++m) {
                    float pr = __shfl_xor_sync(0xffffffffu, vr[m], lm);
                    float pi = __shfl_xor_sync(0xffffffffu, vi[m], lm);
                    float mr = vr[m], mi = vi[m];
                    vr[m] = cg*mr + sg*pi; vi[m] = cg*mi - sg*pr;
                }
            }
        } else {
            #pragma unroll
            for (int m = 0; m < 8; ++m) {
                float pr = __shfl_xor_sync(0xffffffffu, vr[m], lm);
                float pi = __shfl_xor_sync(0xffffffffu, vi[m], lm);
                float mr = vr[m], mi = vi[m];
                float nr = cg*mr + sg*pi, ni = cg*mi - sg*pr;
                vr[m] = act ? nr : mr; vi[m] = act ? ni : mi;
            }
        }
    }
}

// controlled-RX with target = warp bit (WM xor mask); RM = reg mask filter (0 = all regs)
template<int WM, int RM>
__device__ __forceinline__ void applycrxW(float* vr, float* vi, int t7,
    float2 (*ex)[128], float cg, float sg, bool act)
{
    __syncthreads();
    if (act) {
        #pragma unroll
        for (int m = 0; m < 8; ++m) {
            if constexpr (RM != 0) { if (!(m & RM)) continue; }
            ex[m][t7] = make_float2(vr[m], vi[m]);
        }
    }
    __syncthreads();
    if (act) {
        const int p = t7 ^ (WM << 5);
        #pragma unroll
        for (int m = 0; m < 8; ++m) {
            if constexpr (RM != 0) { if (!(m & RM)) continue; }
            float2 pv = ex[m][p];
            float mr = vr[m], mi = vi[m];
            vr[m] = cg*mr + sg*pv.y; vi[m] = cg*mi - sg*pv.x;
        }
    }
}

// ---------------- measurements (per-warp partials) ----------------
template<int B>   // B 0..7
__device__ __forceinline__ void measure(const float* vr, const float* vi, int lane,
                                        float& X, float& Y, float& Z)
{
    float zr = 0.f, zi = 0.f, zd = 0.f;
    if constexpr (B < 3) {
        constexpr int st = 1 << B;
        #pragma unroll
        for (int q = 0; q < 4; ++q) {
            const int m0 = ((q >> B) << (B + 1)) | (q & (st - 1));
            const int m1 = m0 | st;
            zr += vr[m0]*vr[m1] + vi[m0]*vi[m1];
            zi += vr[m0]*vi[m1] - vi[m0]*vr[m1];
            zd += vr[m0]*vr[m0] + vi[m0]*vi[m0] - vr[m1]*vr[m1] - vi[m1]*vi[m1];
        }
        X = 2.f * wred(zr); Y = 2.f * wred(zi); Z = wred(zd);
    } else {
        constexpr int lm = 1 << (B - 3);
        const float sgn = (lane & lm) ? -1.f : 1.f;
        #pragma unroll
        for (int m = 0; m < 8; ++m) {
            float pr = __shfl_xor_sync(0xffffffffu, vr[m], lm);
            float pi = __shfl_xor_sync(0xffffffffu, vi[m], lm);
            float mr = vr[m], mi = vi[m];
            zr += mr*pr + mi*pi;
            zi += mr*pi - mi*pr;
            zd += mr*mr + mi*mi;
        }
        X = wred(zr); Y = wred(zi * sgn); Z = wred(zd * sgn);
    }
}

template<int WM>
__device__ __forceinline__ void measureW(const float* vr, const float* vi, int t7, int w,
    float2 (*ex)[128], float& X, float& Y, float& Z)
{
    __syncthreads();
    #pragma unroll
    for (int m = 0; m < 8; ++m) ex[m][t7] = make_float2(vr[m], vi[m]);
    __syncthreads();
    const int p = t7 ^ (WM << 5);
    const float sgn = (w & WM) ? -1.f : 1.f;
    float zr = 0.f, zi = 0.f, zd = 0.f;
    #pragma unroll
    for (int m = 0; m < 8; ++m) {
        float2 pv = ex[m][p];
        float mr = vr[m], mi = vi[m];
        zr += mr*pv.x + mi*pv.y;
        zi += mr*pv.y - mi*pv.x;
        zd += mr*mr + mi*mi;
    }
    X = wred(zr); Y = wred(zi * sgn); Z = wred(zd * sgn);
}

// ---------------- kernel: one block per (batch, branch), 128 threads = 4 warps ----------------
__global__ void __launch_bounds__(128, 6) qsb_fused(
    const float* __restrict__ x,
    const float* __restrict__ W1, const float* __restrict__ b1, const float* __restrict__ base1,
    const float* __restrict__ W2, const float* __restrict__ b2, const float* __restrict__ base2,
    const float* __restrict__ W3, const float* __restrict__ b3, const float* __restrict__ base3,
    const float* __restrict__ ar_, const float* __restrict__ ai_,
    const float* __restrict__ br_, const float* __restrict__ bi_,
    const float* __restrict__ gr_, const float* __restrict__ gi_,
    float* __restrict__ out)
{
    const int bt   = blockIdx.x & 255;
    const int br   = blockIdx.x >> 8;
    const int t7   = threadIdx.x;        // 0..127
    const int lane = t7 & 31;
    const int w    = t7 >> 5;

    const float* __restrict__ W  = (br == 0) ? W1 : (br == 1) ? W2 : W3;
    const float* __restrict__ bb = (br == 0) ? b1 : (br == 1) ? b2 : b3;
    const float* __restrict__ bs = (br == 0) ? base1 : (br == 1) ? base2 : base3;

    __shared__ __align__(16) float xs[FD];
    __shared__ float2 scs[NP];            // (cos, sin) of half-angle
    __shared__ float2 ex[8][128];
    __shared__ float  mpart[4][NOUT];
    __shared__ int    sIsLast;

    // ---- stage x row ----
    xs[t7]       = x[bt * FD + t7];
    xs[t7 + 128] = x[bt * FD + t7 + 128];
    __syncthreads();

    // ---- params: one thread per param (100 of 128) ----
    if (t7 < NP) {
        const float4* __restrict__ w4 = (const float4*)(W + t7 * FD);
        const float4* __restrict__ x4 = (const float4*)xs;
        float a0 = 0.f, a1 = 0.f, a2 = 0.f, a3 = 0.f;
        #pragma unroll
        for (int k = 0; k < 64; k += 4) {
            float4 wv0 = w4[k],   xv0 = x4[k];
            float4 wv1 = w4[k+1], xv1 = x4[k+1];
            float4 wv2 = w4[k+2], xv2 = x4[k+2];
            float4 wv3 = w4[k+3], xv3 = x4[k+3];
            a0 = fmaf(wv0.x, xv0.x, fmaf(wv0.y, xv0.y, fmaf(wv0.z, xv0.z, fmaf(wv0.w, xv0.w, a0))));
            a1 = fmaf(wv1.x, xv1.x, fmaf(wv1.y, xv1.y, fmaf(wv1.z, xv1.z, fmaf(wv1.w, xv1.w, a1))));
            a2 = fmaf(wv2.x, xv2.x, fmaf(wv2.y, xv2.y, fmaf(wv2.z, xv2.z, fmaf(wv2.w, xv2.w, a2))));
            a3 = fmaf(wv3.x, xv3.x, fmaf(wv3.y, xv3.y, fmaf(wv3.z, xv3.z, fmaf(wv3.w, xv3.w, a3))));
        }
        float t = (a0 + a1) + (a2 + a3) + bb[t7] + bs[t7];
        float half = 3.14159265358979f / (1.0f + __expf(-t));   // (sigmoid*2pi)/2
        float cc2, sn2;
        __sincosf(half, &sn2, &cc2);
        scs[t7] = make_float2(cc2, sn2);
    }
    __syncthreads();

    // ---- circuit ----
    float vr[8], vi[8];
    #pragma unroll
    for (int m = 0; m < 8; ++m) { vr[m] = 0.f; vi[m] = 0.f; }
    if (t7 == 0) vr[0] = 1.0f;

    int idx = 0;

    #define UCOEF \
        float2 p1 = scs[idx], p2 = scs[idx+1], p3 = scs[idx+2]; idx += 3; \
        float c1 = p1.x, s1 = p1.y, c2 = p2.x, s2 = p2.y, c3 = p3.x, s3 = p3.y; \
        float A00r =  c2*c1, A00i =  s2*s1; \
        float A01r = -s2*c1, A01i = -c2*s1; \
        float A10r =  s2*c1, A10i = -c2*s1; \
        float A11r =  c2*c1, A11i = -s2*s1; \
        float U00r = c3*A00r + s3*A00i, U00i = c3*A00i - s3*A00r; \
        float U01r = c3*A01r + s3*A01i, U01i = c3*A01i - s3*A01r; \
        float U10r = c3*A10r - s3*A10i, U10i = c3*A10i + s3*A10r; \
        float U11r = c3*A11r - s3*A11i, U11i = c3*A11i + s3*A11r;

    #define FUSED(B) { UCOEF \
        apply1q<B>(vr, vi, lane, U00r,U00i,U01r,U01i,U10r,U10i,U11r,U11i); }
    #define FUSEDW(WM) { UCOEF \
        apply1qW<WM>(vr, vi, t7, w, ex, U00r,U00i,U01r,U01i,U10r,U10i,U11r,U11i); }
    #define CRX(BC,BT) { float2 p = scs[idx]; idx++; \
        applycrx<BC,BT>(vr, vi, lane, w, p.x, p.y); }
    #define CRXW(WM,RM,ACT) { float2 p = scs[idx]; idx++; \
        applycrxW<WM,RM>(vr, vi, t7, ex, p.x, p.y, (ACT)); }

    #pragma unroll 1
    for (int layer = 0; layer < 2; ++layer) {
        // 1q triples, wires 0..9 -> bits 9..0
        FUSEDW(2) FUSEDW(1)
        FUSED(7) FUSED(6) FUSED(5) FUSED(4)
        FUSED(3) FUSED(2) FUSED(1) FUSED(0)
        // forward ring (bit space): (9,8)(8,7)(7,6)(6,5)(5,4)(4,3)(3,2)(2,1)(1,0)(0,9)
        CRXW(1, 0, (w & 2) != 0)                 // control bit9, target bit8
        CRX(8,7) CRX(7,6) CRX(6,5) CRX(5,4)
        CRX(4,3) CRX(3,2) CRX(2,1) CRX(1,0)
        CRXW(2, 1, true)                          // control reg bit0, target bit9
        // backward ring: (0,1)(1,2)(2,3)(3,4)(4,5)(5,6)(6,7)(7,8)(8,9)(9,0)
        CRX(0,1) CRX(1,2) CRX(2,3) CRX(3,4)
        CRX(4,5) CRX(5,6) CRX(6,7)
        CRXW(1, 0, (lane & 16) != 0)              // control bit7 (lane), target bit8
        CRXW(2, 0, (w & 1) != 0)                  // control bit8, target bit9
        CRX(9,0)                                  // control bit9 (warp), target reg bit0
    }

    // ---- measurements (wire v -> bit 9-v) ----
    {
        float X, Y, Z;
        measureW<2>(vr, vi, t7, w, ex, X, Y, Z);   // wire 0 (bit 9)
        if (lane == 0) { mpart[w][0] = X; mpart[w][10] = Y; mpart[w][20] = Z; }
    }
    {
        float X, Y, Z;
        measureW<1>(vr, vi, t7, w, ex, X, Y, Z);   // wire 1 (bit 8)
        if (lane == 0) { mpart[w][1] = X; mpart[w][11] = Y; mpart[w][21] = Z; }
    }
    #define MEAS(v) { float X, Y, Z; measure<9-(v)>(vr, vi, lane, X, Y, Z); \
        if (lane == 0) { mpart[w][v] = X; mpart[w][10+(v)] = Y; mpart[w][20+(v)] = Z; } }
    MEAS(2) MEAS(3) MEAS(4) MEAS(5) MEAS(6) MEAS(7) MEAS(8) MEAS(9)
    __syncthreads();

    // ---- publish per-branch expvals, last-block combine ----
    if (t7 < NOUT) {
        float s = (mpart[0][t7] + mpart[1][t7]) + (mpart[2][t7] + mpart[3][t7]);
        g_m[br][bt][t7] = s;
        __threadfence();
    }
    __syncthreads();
    if (t7 == 0) {
        unsigned int old = atomicAdd(&g_cnt[bt], 1u);
        sIsLast = (old == 2u);
    }
    __syncthreads();
    if (sIsLast) {
        if (t7 < NOUT) {
            __threadfence();
            float m1 = g_m[0][bt][t7];
            float m2 = g_m[1][bt][t7];
            float m3 = g_m[2][bt][t7];
            float ar = ar_[0], ai = ai_[0];
            float brv = br_[0], bi = bi_[0];
            float gr = gr_[0], gi = gi_[0];
            float norm = sqrtf(ar*ar + ai*ai + brv*brv + bi*bi + gr*gr + gi*gi + 1e-9f);
            float re = (ar * m1 + brv * m2 + gr * m3) / norm;
            float im = (ai * m1 + bi * m2 + gi * m3) / norm;
            out[bt * NOUT + t7] = sqrtf(re * re + im * im);
        }
        if (t7 == 0) g_cnt[bt] = 0u;   // reset for next graph replay
    }
}

extern "C" void kernel_launch(void* const* d_in, const int* in_sizes, int n_in,
                              void* d_out, int out_size)
{
    // d_in order: x, W1, b1, W2, b2, W3, b3, base1, base2, base3, ar, ai, br, bi, gr, gi
    qsb_fused<<<3 * BATCH, 128>>>(
        (const float*)d_in[0],
        (const float*)d_in[1], (const float*)d_in[2], (const float*)d_in[7],
        (const float*)d_in[3], (const float*)d_in[4], (const float*)d_in[8],
        (const float*)d_in[5], (const float*)d_in[6], (const float*)d_in[9],
        (const float*)d_in[10], (const float*)d_in[11],
        (const float*)d_in[12], (const float*)d_in[13],
        (const float*)d_in[14], (const float*)d_in[15],
        (float*)d_out);
}

// round 9
// speedup vs baseline: 1.1658x; 1.0513x over previous
#include <cuda_runtime.h>
#include <math.h>

#define NP     100
#define BATCH  256
#define FD     256
#define NOUT   30

// Storage map (wire -> storage bit): regs bits 0..2, lanes 3..7, warps 8..9
//  wire: 0   1   2   3   4   5   6   7   8   9
//  bit : 7   2   6   1   5   0   4   8   3   9
// Ring-alternating so every lane-target CRX has a reg/warp control.

// per-circuit barrier: 4 warps, 128 threads, ids 1..3
__device__ __forceinline__ void barc(int c) {
    asm volatile("bar.sync %0, 128;" :: "r"(c + 1) : "memory");
}

__device__ __forceinline__ float wred(float v) {
    #pragma unroll
    for (int o = 16; o; o >>= 1) v += __shfl_xor_sync(0xffffffffu, v, o);
    return v;
}

// ---------------- 1q gate, storage bit B in 0..7 ----------------
template<int B>
__device__ __forceinline__ void apply1q(float* vr, float* vi, int lane,
    float U00r, float U00i, float U01r, float U01i,
    float U10r, float U10i, float U11r, float U11i)
{
    if constexpr (B < 3) {
        constexpr int st = 1 << B;
        #pragma unroll
        for (int q = 0; q < 4; ++q) {
            const int m0 = ((q >> B) << (B + 1)) | (q & (st - 1));
            const int m1 = m0 | st;
            float a0r = vr[m0], a0i = vi[m0], a1r = vr[m1], a1i = vi[m1];
            vr[m0] = U00r*a0r - U00i*a0i + U01r*a1r - U01i*a1i;
            vi[m0] = U00r*a0i + U00i*a0r + U01r*a1i + U01i*a1r;
            vr[m1] = U10r*a0r - U10i*a0i + U11r*a1r - U11i*a1i;
            vi[m1] = U10r*a0i + U10i*a0r + U11r*a1i + U11i*a1r;
        }
    } else {
        constexpr int lm = 1 << (B - 3);
        const bool r = (lane & lm) != 0;
        float cmr = r ? U11r : U00r, cmi = r ? U11i : U00i;
        float cpr = r ? U10r : U01r, cpi = r ? U10i : U01i;
        #pragma unroll
        for (int m = 0; m < 8; ++m) {
            float pr = __shfl_xor_sync(0xffffffffu, vr[m], lm);
            float pi = __shfl_xor_sync(0xffffffffu, vi[m], lm);
            float mr = vr[m], mi = vi[m];
            vr[m] = cmr*mr - cmi*mi + cpr*pr - cpi*pi;
            vi[m] = cmr*mi + cmi*mr + cpr*pi + cpi*pr;
        }
    }
}

// 1q gate on warp bit (WM=1 -> bit8, WM=2 -> bit9), float2 smem exchange
template<int WM>
__device__ __forceinline__ void apply1qW(float* vr, float* vi, int cc, int t7, int w,
    float2 (*ex)[128],
    float U00r, float U00i, float U01r, float U01i,
    float U10r, float U10i, float U11r, float U11i)
{
    const bool hi = (w & WM) != 0;
    float cmr = hi ? U11r : U00r, cmi = hi ? U11i : U00i;
    float cpr = hi ? U10r : U01r, cpi = hi ? U10i : U01i;
    barc(cc);
    #pragma unroll
    for (int m = 0; m < 8; ++m) ex[m][t7] = make_float2(vr[m], vi[m]);
    barc(cc);
    const int p = t7 ^ (WM << 5);
    #pragma unroll
    for (int m = 0; m < 8; ++m) {
        float2 pv = ex[m][p];
        float mr = vr[m], mi = vi[m];
        vr[m] = cmr*mr - cmi*mi + cpr*pv.x - cpi*pv.y;
        vi[m] = cmr*mi + cmi*mr + cpr*pv.y + cpi*pv.x;
    }
}

// ---------------- controlled-RX, target BT <= 7, control BC in 0..9 ----------------
template<int BC, int BT>
__device__ __forceinline__ void applycrx(float* vr, float* vi, int lane, int w, float cg, float sg)
{
    bool act = true;
    if constexpr (BC >= 8)      act = (w & (1 << (BC - 8))) != 0;
    else if constexpr (BC >= 3) act = (lane & (1 << (BC - 3))) != 0;

    if constexpr (BT < 3) {
        constexpr int tm = 1 << BT;
        if constexpr (BC < 3) {
            #pragma unroll
            for (int m0 = 0; m0 < 8; ++m0)
                if ((m0 & (1 << BC)) && !(m0 & tm)) {
                    const int m1 = m0 | tm;
                    float a0r = vr[m0], a0i = vi[m0], a1r = vr[m1], a1i = vi[m1];
                    vr[m0] = cg*a0r + sg*a1i; vi[m0] = cg*a0i - sg*a1r;
                    vr[m1] = cg*a1r + sg*a0i; vi[m1] = cg*a1i - sg*a0r;
                }
        } else {
            if (act) {
                #pragma unroll
                for (int q = 0; q < 4; ++q) {
                    const int m0 = ((q >> BT) << (BT + 1)) | (q & (tm - 1));
                    const int m1 = m0 | tm;
                    float a0r = vr[m0], a0i = vi[m0], a1r = vr[m1], a1i = vi[m1];
                    vr[m0] = cg*a0r + sg*a1i; vi[m0] = cg*a0i - sg*a1r;
                    vr[m1] = cg*a1r + sg*a0i; vi[m1] = cg*a1i - sg*a0r;
                }
            }
        }
    } else {
        constexpr int lm = 1 << (BT - 3);
        if constexpr (BC < 3) {
            // only regs with control bit set participate: 4 regs -> 8 SHFL
            #pragma unroll
            for (int m = 0; m < 8; ++m)
                if (m & (1 << BC)) {
                    float pr = __shfl_xor_sync(0xffffffffu, vr[m], lm);
                    float pi = __shfl_xor_sync(0xffffffffu, vi[m], lm);
                    float mr = vr[m], mi = vi[m];
                    vr[m] = cg*mr + sg*pi; vi[m] = cg*mi - sg*pr;
                }
        } else if constexpr (BC >= 8) {
            if (act) {   // warp-uniform predicate: only active warps issue SHFL
                #pragma unroll
                for (int m = 0; m < 8; ++m) {
                    float pr = __shfl_xor_sync(0xffffffffu, vr[m], lm);
                    float pi = __shfl_xor_sync(0xffffffffu, vi[m], lm);
                    float mr = vr[m], mi = vi[m];
                    vr[m] = cg*mr + sg*pi; vi[m] = cg*mi - sg*pr;
                }
            }
        } else {
            #pragma unroll
            for (int m = 0; m < 8; ++m) {
                float pr = __shfl_xor_sync(0xffffffffu, vr[m], lm);
                float pi = __shfl_xor_sync(0xffffffffu, vi[m], lm);
                float mr = vr[m], mi = vi[m];
                float nr = cg*mr + sg*pi, ni = cg*mi - sg*pr;
                vr[m] = act ? nr : mr; vi[m] = act ? ni : mi;
            }
        }
    }
}

// controlled-RX with target = warp bit (WM); act = control predicate (lane-based)
template<int WM>
__device__ __forceinline__ void applycrxW(float* vr, float* vi, int cc, int t7,
    float2 (*ex)[128], float cg, float sg, bool act)
{
    barc(cc);
    if (act) {
        #pragma unroll
        for (int m = 0; m < 8; ++m) ex[m][t7] = make_float2(vr[m], vi[m]);
    }
    barc(cc);
    if (act) {
        const int p = t7 ^ (WM << 5);
        #pragma unroll
        for (int m = 0; m < 8; ++m) {
            float2 pv = ex[m][p];
            float mr = vr[m], mi = vi[m];
            vr[m] = cg*mr + sg*pv.y; vi[m] = cg*mi - sg*pv.x;
        }
    }
}

// ---------------- measurements (per-warp partials) ----------------
template<int B>   // storage bit 0..7
__device__ __forceinline__ void measure(const float* vr, const float* vi, int lane,
                                        float& X, float& Y, float& Z)
{
    float zr = 0.f, zi = 0.f, zd = 0.f;
    if constexpr (B < 3) {
        constexpr int st = 1 << B;
        #pragma unroll
        for (int q = 0; q < 4; ++q) {
            const int m0 = ((q >> B) << (B + 1)) | (q & (st - 1));
            const int m1 = m0 | st;
            zr += vr[m0]*vr[m1] + vi[m0]*vi[m1];
            zi += vr[m0]*vi[m1] - vi[m0]*vr[m1];
            zd += vr[m0]*vr[m0] + vi[m0]*vi[m0] - vr[m1]*vr[m1] - vi[m1]*vi[m1];
        }
        X = 2.f * wred(zr); Y = 2.f * wred(zi); Z = wred(zd);
    } else {
        constexpr int lm = 1 << (B - 3);
        const float sgn = (lane & lm) ? -1.f : 1.f;
        #pragma unroll
        for (int m = 0; m < 8; ++m) {
            float pr = __shfl_xor_sync(0xffffffffu, vr[m], lm);
            float pi = __shfl_xor_sync(0xffffffffu, vi[m], lm);
            float mr = vr[m], mi = vi[m];
            zr += mr*pr + mi*pi;
            zi += mr*pi - mi*pr;
            zd += mr*mr + mi*mi;
        }
        X = wred(zr); Y = wred(zi * sgn); Z = wred(zd * sgn);
    }
}

template<int WM>
__device__ __forceinline__ void measureW(const float* vr, const float* vi, int cc, int t7, int w,
    float2 (*ex)[128], float& X, float& Y, float& Z)
{
    barc(cc);
    #pragma unroll
    for (int m = 0; m < 8; ++m) ex[m][t7] = make_float2(vr[m], vi[m]);
    barc(cc);
    const int p = t7 ^ (WM << 5);
    const float sgn = (w & WM) ? -1.f : 1.f;
    float zr = 0.f, zi = 0.f, zd = 0.f;
    #pragma unroll
    for (int m = 0; m < 8; ++m) {
        float2 pv = ex[m][p];
        float mr = vr[m], mi = vi[m];
        zr += mr*pv.x + mi*pv.y;
        zi += mr*pv.y - mi*pv.x;
        zd += mr*mr + mi*mi;
    }
    X = wred(zr); Y = wred(zi * sgn); Z = wred(zd * sgn);
}

// ---------------- fused kernel: one block per batch element ----------------
// block = 384 threads = 3 circuits (branches) x 4 warps
__global__ void __launch_bounds__(384) qsb_fused(
    const float* __restrict__ x,
    const float* __restrict__ W1, const float* __restrict__ b1, const float* __restrict__ base1,
    const float* __restrict__ W2, const float* __restrict__ b2, const float* __restrict__ base2,
    const float* __restrict__ W3, const float* __restrict__ b3, const float* __restrict__ base3,
    const float* __restrict__ ar_, const float* __restrict__ ai_,
    const float* __restrict__ br_, const float* __restrict__ bi_,
    const float* __restrict__ gr_, const float* __restrict__ gi_,
    float* __restrict__ out)
{
    const int bt   = blockIdx.x;
    const int tid  = threadIdx.x;
    const int lane = tid & 31;

    __shared__ __align__(16) float xs[FD];
    __shared__ float2 scs[3 * NP];
    __shared__ float2 ex[3][8][128];
    __shared__ float  mpart[3][4][NOUT];

    // ---- stage x row ----
    for (int k = tid; k < FD; k += 384) xs[k] = x[bt * FD + k];
    __syncthreads();

    // ---- params: one thread per param (300 of 384) ----
    if (tid < 3 * NP) {
        const int br2 = (tid < NP) ? 0 : ((tid < 2 * NP) ? 1 : 2);
        const int j = tid - br2 * NP;
        const float* __restrict__ W  = (br2 == 0) ? W1 : (br2 == 1) ? W2 : W3;
        const float* __restrict__ bb = (br2 == 0) ? b1 : (br2 == 1) ? b2 : b3;
        const float* __restrict__ bs = (br2 == 0) ? base1 : (br2 == 1) ? base2 : base3;
        const float4* __restrict__ w4 = (const float4*)(W + j * FD);
        const float4* __restrict__ x4 = (const float4*)xs;
        float a0 = 0.f, a1 = 0.f, a2 = 0.f, a3 = 0.f;
        #pragma unroll
        for (int k = 0; k < 64; k += 4) {
            float4 wv0 = w4[k],   xv0 = x4[k];
            float4 wv1 = w4[k+1], xv1 = x4[k+1];
            float4 wv2 = w4[k+2], xv2 = x4[k+2];
            float4 wv3 = w4[k+3], xv3 = x4[k+3];
            a0 = fmaf(wv0.x, xv0.x, fmaf(wv0.y, xv0.y, fmaf(wv0.z, xv0.z, fmaf(wv0.w, xv0.w, a0))));
            a1 = fmaf(wv1.x, xv1.x, fmaf(wv1.y, xv1.y, fmaf(wv1.z, xv1.z, fmaf(wv1.w, xv1.w, a1))));
            a2 = fmaf(wv2.x, xv2.x, fmaf(wv2.y, xv2.y, fmaf(wv2.z, xv2.z, fmaf(wv2.w, xv2.w, a2))));
            a3 = fmaf(wv3.x, xv3.x, fmaf(wv3.y, xv3.y, fmaf(wv3.z, xv3.z, fmaf(wv3.w, xv3.w, a3))));
        }
        float t = (a0 + a1) + (a2 + a3) + bb[j] + bs[j];
        float half = 3.14159265358979f / (1.0f + __expf(-t));   // (sigmoid*2pi)/2
        float cc2, sn2;
        __sincosf(half, &sn2, &cc2);
        scs[tid] = make_float2(cc2, sn2);
    }
    __syncthreads();

    // ---- circuit ----
    const int cc = tid >> 7;          // circuit / branch
    const int t7 = tid & 127;
    const int w  = t7 >> 5;           // warp within circuit (storage bits 8,9)
    const float2* __restrict__ pcs = &scs[cc * NP];
    float2 (*bufr)[128] = ex[cc];

    float vr[8], vi[8];
    #pragma unroll
    for (int m = 0; m < 8; ++m) { vr[m] = 0.f; vi[m] = 0.f; }
    if (t7 == 0) vr[0] = 1.0f;

    int idx = 0;

    #define UCOEF \
        float2 p1 = pcs[idx], p2 = pcs[idx+1], p3 = pcs[idx+2]; idx += 3; \
        float c1 = p1.x, s1 = p1.y, c2 = p2.x, s2 = p2.y, c3 = p3.x, s3 = p3.y; \
        float A00r =  c2*c1, A00i =  s2*s1; \
        float A01r = -s2*c1, A01i = -c2*s1; \
        float A10r =  s2*c1, A10i = -c2*s1; \
        float A11r =  c2*c1, A11i = -s2*s1; \
        float U00r = c3*A00r + s3*A00i, U00i = c3*A00i - s3*A00r; \
        float U01r = c3*A01r + s3*A01i, U01i = c3*A01i - s3*A01r; \
        float U10r = c3*A10r - s3*A10i, U10i = c3*A10i + s3*A10r; \
        float U11r = c3*A11r - s3*A11i, U11i = c3*A11i + s3*A11r;

    #define FUSED(B) { UCOEF \
        apply1q<B>(vr, vi, lane, U00r,U00i,U01r,U01i,U10r,U10i,U11r,U11i); }
    #define FUSEDW(WM) { UCOEF \
        apply1qW<WM>(vr, vi, cc, t7, w, bufr, U00r,U00i,U01r,U01i,U10r,U10i,U11r,U11i); }
    #define CRX(BC,BT) { float2 p = pcs[idx]; idx++; \
        applycrx<BC,BT>(vr, vi, lane, w, p.x, p.y); }
    #define CRXW(WM,ACT) { float2 p = pcs[idx]; idx++; \
        applycrxW<WM>(vr, vi, cc, t7, bufr, p.x, p.y, (ACT)); }

    // wire -> storage bit: 0:7 1:2 2:6 3:1 4:5 5:0 6:4 7:W8 8:3 9:W9
    #pragma unroll 1
    for (int layer = 0; layer < 2; ++layer) {
        // 1q triples, wire order 0..9
        FUSED(7) FUSED(2) FUSED(6) FUSED(1) FUSED(5)
        FUSED(0) FUSED(4) FUSEDW(1) FUSED(3) FUSEDW(2)
        // forward ring: control i, target i+1 (wire space)
        CRX(7,2)                          // (0,1)
        CRX(2,6)                          // (1,2)
        CRX(6,1)                          // (2,3)
        CRX(1,5)                          // (3,4)
        CRX(5,0)                          // (4,5)
        CRX(0,4)                          // (5,6)
        CRXW(1, (lane & 2) != 0)          // (6,7): ctrl lane bit1 (storage 4), tgt bit8
        CRX(8,3)                          // (7,8)
        CRXW(2, (lane & 1) != 0)          // (8,9): ctrl lane bit0 (storage 3), tgt bit9
        CRX(9,7)                          // (9,0)
        // backward ring: control i, target i-1, i = 9..0
        CRX(9,3)                          // (9,8)
        CRXW(1, (lane & 1) != 0)          // (8,7): ctrl storage 3, tgt bit8
        CRX(8,4)                          // (7,6)
        CRX(4,0)                          // (6,5)
        CRX(0,5)                          // (5,4)
        CRX(5,1)                          // (4,3)
        CRX(1,6)                          // (3,2)
        CRX(6,2)                          // (2,1)
        CRX(2,7)                          // (1,0)
        CRXW(2, (lane & 16) != 0)         // (0,9): ctrl storage 7, tgt bit9
    }

    // ---- measurements (wire -> storage bit) ----
    {
        float X, Y, Z;
        measureW<1>(vr, vi, cc, t7, w, bufr, X, Y, Z);       // wire 7 (bit 8)
        if (lane == 0) { mpart[cc][w][7] = X; mpart[cc][w][17] = Y; mpart[cc][w][27] = Z; }
    }
    {
        float X, Y, Z;
        measureW<2>(vr, vi, cc, t7, w, bufr, X, Y, Z);       // wire 9 (bit 9)
        if (lane == 0) { mpart[cc][w][9] = X; mpart[cc][w][19] = Y; mpart[cc][w][29] = Z; }
    }
    #define MEAS(v,B) { float X, Y, Z; measure<B>(vr, vi, lane, X, Y, Z); \
        if (lane == 0) { mpart[cc][w][v] = X; mpart[cc][w][10+(v)] = Y; mpart[cc][w][20+(v)] = Z; } }
    MEAS(0,7) MEAS(1,2) MEAS(2,6) MEAS(3,1) MEAS(4,5)
    MEAS(5,0) MEAS(6,4) MEAS(8,3)

    // ---- combine ----
    __syncthreads();
    if (tid < NOUT) {
        const int k = tid;
        float m1 = (mpart[0][0][k] + mpart[0][1][k]) + (mpart[0][2][k] + mpart[0][3][k]);
        float m2 = (mpart[1][0][k] + mpart[1][1][k]) + (mpart[1][2][k] + mpart[1][3][k]);
        float m3 = (mpart[2][0][k] + mpart[2][1][k]) + (mpart[2][2][k] + mpart[2][3][k]);
        float ar = ar_[0], ai = ai_[0];
        float brv = br_[0], bi = bi_[0];
        float gr = gr_[0], gi = gi_[0];
        float norm = sqrtf(ar*ar + ai*ai + brv*brv + bi*bi + gr*gr + gi*gi + 1e-9f);
        float re = (ar * m1 + brv * m2 + gr * m3) / norm;
        float im = (ai * m1 + bi * m2 + gi * m3) / norm;
        out[bt * NOUT + k] = sqrtf(re * re + im * im);
    }
}

extern "C" void kernel_launch(void* const* d_in, const int* in_sizes, int n_in,
                              void* d_out, int out_size)
{
    // d_in order: x, W1, b1, W2, b2, W3, b3, base1, base2, base3, ar, ai, br, bi, gr, gi
    qsb_fused<<<BATCH, 384>>>(
        (const float*)d_in[0],
        (const float*)d_in[1], (const float*)d_in[2], (const float*)d_in[7],
        (const float*)d_in[3], (const float*)d_in[4], (const float*)d_in[8],
        (const float*)d_in[5], (const float*)d_in[6], (const float*)d_in[9],
        (const float*)d_in[10], (const float*)d_in[11],
        (const float*)d_in[12], (const float*)d_in[13],
        (const float*)d_in[14], (const float*)d_in[15],
        (float*)d_out);
}

// round 10
// speedup vs baseline: 1.4204x; 1.2183x over previous
#include <cuda_runtime.h>
#include <math.h>

#define NP     100
#define BATCH  256
#define FD     256
#define NOUT   30

// precomputed (cos, sin) of half-angles: [batch][branch*100 + j]
__device__ float2 g_scs[BATCH][3 * NP];

// ---------------- kernel 1: coalesced param GEMM + sincos ----------------
// one block per param row jj (300 blocks), 8 warps x 32 batches
__global__ void __launch_bounds__(256) qsb_params(
    const float* __restrict__ x,
    const float* __restrict__ W1, const float* __restrict__ b1, const float* __restrict__ base1,
    const float* __restrict__ W2, const float* __restrict__ b2, const float* __restrict__ base2,
    const float* __restrict__ W3, const float* __restrict__ b3, const float* __restrict__ base3)
{
    const int jj = blockIdx.x;                       // 0..299
    const int br = (jj < NP) ? 0 : ((jj < 2 * NP) ? 1 : 2);
    const int j  = jj - br * NP;
    const float* __restrict__ W  = (br == 0) ? W1 : (br == 1) ? W2 : W3;
    const float* __restrict__ bb = (br == 0) ? b1 : (br == 1) ? b2 : b3;
    const float* __restrict__ bs = (br == 0) ? base1 : (br == 1) ? base2 : base3;

    const int lane = threadIdx.x & 31;
    const int wid  = threadIdx.x >> 5;               // 0..7

    // W row cached in registers (coalesced)
    const float4* __restrict__ w4 = (const float4*)(W + j * FD);
    const float4 wa = w4[lane];
    const float4 wb = w4[lane + 32];
    const float bias = bb[j] + bs[j];

    // each warp handles 32 batch elements
    #pragma unroll 2
    for (int t = 0; t < 32; ++t) {
        const int bt = wid * 32 + t;
        const float4* __restrict__ x4 = (const float4*)(x + bt * FD);
        float4 xa = x4[lane];
        float4 xb = x4[lane + 32];
        float s = wa.x*xa.x + wa.y*xa.y + wa.z*xa.z + wa.w*xa.w
                + wb.x*xb.x + wb.y*xb.y + wb.z*xb.z + wb.w*xb.w;
        #pragma unroll
        for (int o = 16; o; o >>= 1) s += __shfl_xor_sync(0xffffffffu, s, o);
        if (lane == 0) {
            float tt = s + bias;
            float half = 3.14159265358979f / (1.0f + __expf(-tt));   // (sigmoid*2pi)/2
            float cc2, sn2;
            __sincosf(half, &sn2, &cc2);
            g_scs[bt][jj] = make_float2(cc2, sn2);
        }
    }
}

// ---------------- circuit machinery ----------------
// Storage map (wire -> storage bit): regs bits 0..2, lanes 3..7, warps 8..9
//  wire: 0   1   2   3   4   5   6   7   8   9
//  bit : 7   2   6   1   5   0   4   8   3   9

__device__ __forceinline__ void barc(int c) {
    asm volatile("bar.sync %0, 128;" :: "r"(c + 1) : "memory");
}

__device__ __forceinline__ float wred(float v) {
    #pragma unroll
    for (int o = 16; o; o >>= 1) v += __shfl_xor_sync(0xffffffffu, v, o);
    return v;
}

template<int B>
__device__ __forceinline__ void apply1q(float* vr, float* vi, int lane,
    float U00r, float U00i, float U01r, float U01i,
    float U10r, float U10i, float U11r, float U11i)
{
    if constexpr (B < 3) {
        constexpr int st = 1 << B;
        #pragma unroll
        for (int q = 0; q < 4; ++q) {
            const int m0 = ((q >> B) << (B + 1)) | (q & (st - 1));
            const int m1 = m0 | st;
            float a0r = vr[m0], a0i = vi[m0], a1r = vr[m1], a1i = vi[m1];
            vr[m0] = U00r*a0r - U00i*a0i + U01r*a1r - U01i*a1i;
            vi[m0] = U00r*a0i + U00i*a0r + U01r*a1i + U01i*a1r;
            vr[m1] = U10r*a0r - U10i*a0i + U11r*a1r - U11i*a1i;
            vi[m1] = U10r*a0i + U10i*a0r + U11r*a1i + U11i*a1r;
        }
    } else {
        constexpr int lm = 1 << (B - 3);
        const bool r = (lane & lm) != 0;
        float cmr = r ? U11r : U00r, cmi = r ? U11i : U00i;
        float cpr = r ? U10r : U01r, cpi = r ? U10i : U01i;
        #pragma unroll
        for (int m = 0; m < 8; ++m) {
            float pr = __shfl_xor_sync(0xffffffffu, vr[m], lm);
            float pi = __shfl_xor_sync(0xffffffffu, vi[m], lm);
            float mr = vr[m], mi = vi[m];
            vr[m] = cmr*mr - cmi*mi + cpr*pr - cpi*pi;
            vi[m] = cmr*mi + cmi*mr + cpr*pi + cpi*pr;
        }
    }
}

template<int WM>
__device__ __forceinline__ void apply1qW(float* vr, float* vi, int cc, int t7, int w,
    float2 (*ex)[128],
    float U00r, float U00i, float U01r, float U01i,
    float U10r, float U10i, float U11r, float U11i)
{
    const bool hi = (w & WM) != 0;
    float cmr = hi ? U11r : U00r, cmi = hi ? U11i : U00i;
    float cpr = hi ? U10r : U01r, cpi = hi ? U10i : U01i;
    barc(cc);
    #pragma unroll
    for (int m = 0; m < 8; ++m) ex[m][t7] = make_float2(vr[m], vi[m]);
    barc(cc);
    const int p = t7 ^ (WM << 5);
    #pragma unroll
    for (int m = 0; m < 8; ++m) {
        float2 pv = ex[m][p];
        float mr = vr[m], mi = vi[m];
        vr[m] = cmr*mr - cmi*mi + cpr*pv.x - cpi*pv.y;
        vi[m] = cmr*mi + cmi*mr + cpr*pv.y + cpi*pv.x;
    }
}

template<int BC, int BT>
__device__ __forceinline__ void applycrx(float* vr, float* vi, int lane, int w, float cg, float sg)
{
    bool act = true;
    if constexpr (BC >= 8)      act = (w & (1 << (BC - 8))) != 0;
    else if constexpr (BC >= 3) act = (lane & (1 << (BC - 3))) != 0;

    if constexpr (BT < 3) {
        constexpr int tm = 1 << BT;
        if constexpr (BC < 3) {
            #pragma unroll
            for (int m0 = 0; m0 < 8; ++m0)
                if ((m0 & (1 << BC)) && !(m0 & tm)) {
                    const int m1 = m0 | tm;
                    float a0r = vr[m0], a0i = vi[m0], a1r = vr[m1], a1i = vi[m1];
                    vr[m0] = cg*a0r + sg*a1i; vi[m0] = cg*a0i - sg*a1r;
                    vr[m1] = cg*a1r + sg*a0i; vi[m1] = cg*a1i - sg*a0r;
                }
        } else {
            if (act) {
                #pragma unroll
                for (int q = 0; q < 4; ++q) {
                    const int m0 = ((q >> BT) << (BT + 1)) | (q & (tm - 1));
                    const int m1 = m0 | tm;
                    float a0r = vr[m0], a0i = vi[m0], a1r = vr[m1], a1i = vi[m1];
                    vr[m0] = cg*a0r + sg*a1i; vi[m0] = cg*a0i - sg*a1r;
                    vr[m1] = cg*a1r + sg*a0i; vi[m1] = cg*a1i - sg*a0r;
                }
            }
        }
    } else {
        constexpr int lm = 1 << (BT - 3);
        if constexpr (BC < 3) {
            #pragma unroll
            for (int m = 0; m < 8; ++m)
                if (m & (1 << BC)) {
                    float pr = __shfl_xor_sync(0xffffffffu, vr[m], lm);
                    float pi = __shfl_xor_sync(0xffffffffu, vi[m], lm);
                    float mr = vr[m], mi = vi[m];
                    vr[m] = cg*mr + sg*pi; vi[m] = cg*mi - sg*pr;
                }
        } else if constexpr (BC >= 8) {
            if (act) {
                #pragma unroll
                for (int m = 0; m < 8; ++m) {
                    float pr = __shfl_xor_sync(0xffffffffu, vr[m], lm);
                    float pi = __shfl_xor_sync(0xffffffffu, vi[m], lm);
                    float mr = vr[m], mi = vi[m];
                    vr[m] = cg*mr + sg*pi; vi[m] = cg*mi - sg*pr;
                }
            }
        } else {
            #pragma unroll
            for (int m = 0; m < 8; ++m) {
                float pr = __shfl_xor_sync(0xffffffffu, vr[m], lm);
                float pi = __shfl_xor_sync(0xffffffffu, vi[m], lm);
                float mr = vr[m], mi = vi[m];
                float nr = cg*mr + sg*pi, ni = cg*mi - sg*pr;
                vr[m] = act ? nr : mr; vi[m] = act ? ni : mi;
            }
        }
    }
}

template<int WM>
__device__ __forceinline__ void applycrxW(float* vr, float* vi, int cc, int t7,
    float2 (*ex)[128], float cg, float sg, bool act)
{
    barc(cc);
    if (act) {
        #pragma unroll
        for (int m = 0; m < 8; ++m) ex[m][t7] = make_float2(vr[m], vi[m]);
    }
    barc(cc);
    if (act) {
        const int p = t7 ^ (WM << 5);
        #pragma unroll
        for (int m = 0; m < 8; ++m) {
            float2 pv = ex[m][p];
            float mr = vr[m], mi = vi[m];
            vr[m] = cg*mr + sg*pv.y; vi[m] = cg*mi - sg*pv.x;
        }
    }
}

template<int B>
__device__ __forceinline__ void measure(const float* vr, const float* vi, int lane,
                                        float& X, float& Y, float& Z)
{
    float zr = 0.f, zi = 0.f, zd = 0.f;
    if constexpr (B < 3) {
        constexpr int st = 1 << B;
        #pragma unroll
        for (int q = 0; q < 4; ++q) {
            const int m0 = ((q >> B) << (B + 1)) | (q & (st - 1));
            const int m1 = m0 | st;
            zr += vr[m0]*vr[m1] + vi[m0]*vi[m1];
            zi += vr[m0]*vi[m1] - vi[m0]*vr[m1];
            zd += vr[m0]*vr[m0] + vi[m0]*vi[m0] - vr[m1]*vr[m1] - vi[m1]*vi[m1];
        }
        X = 2.f * wred(zr); Y = 2.f * wred(zi); Z = wred(zd);
    } else {
        constexpr int lm = 1 << (B - 3);
        const float sgn = (lane & lm) ? -1.f : 1.f;
        #pragma unroll
        for (int m = 0; m < 8; ++m) {
            float pr = __shfl_xor_sync(0xffffffffu, vr[m], lm);
            float pi = __shfl_xor_sync(0xffffffffu, vi[m], lm);
            float mr = vr[m], mi = vi[m];
            zr += mr*pr + mi*pi;
            zi += mr*pi - mi*pr;
            zd += mr*mr + mi*mi;
        }
        X = wred(zr); Y = wred(zi * sgn); Z = wred(zd * sgn);
    }
}

template<int WM>
__device__ __forceinline__ void measureW(const float* vr, const float* vi, int cc, int t7, int w,
    float2 (*ex)[128], float& X, float& Y, float& Z)
{
    barc(cc);
    #pragma unroll
    for (int m = 0; m < 8; ++m) ex[m][t7] = make_float2(vr[m], vi[m]);
    barc(cc);
    const int p = t7 ^ (WM << 5);
    const float sgn = (w & WM) ? -1.f : 1.f;
    float zr = 0.f, zi = 0.f, zd = 0.f;
    #pragma unroll
    for (int m = 0; m < 8; ++m) {
        float2 pv = ex[m][p];
        float mr = vr[m], mi = vi[m];
        zr += mr*pv.x + mi*pv.y;
        zi += mr*pv.y - mi*pv.x;
        zd += mr*mr + mi*mi;
    }
    X = wred(zr); Y = wred(zi * sgn); Z = wred(zd * sgn);
}

// ---------------- kernel 2: circuits + combine ----------------
// block = 384 threads = 3 circuits (branches) x 4 warps, one block per batch element
__global__ void __launch_bounds__(384) qsb_circuit(
    const float* __restrict__ ar_, const float* __restrict__ ai_,
    const float* __restrict__ br_, const float* __restrict__ bi_,
    const float* __restrict__ gr_, const float* __restrict__ gi_,
    float* __restrict__ out)
{
    const int bt   = blockIdx.x;
    const int tid  = threadIdx.x;
    const int lane = tid & 31;

    __shared__ float2 scs[3 * NP];
    __shared__ float2 ex[3][8][128];
    __shared__ float  mpart[3][4][NOUT];

    // stage precomputed (cos,sin): 300 consecutive float2 = coalesced
    if (tid < 3 * NP) scs[tid] = g_scs[bt][tid];
    __syncthreads();

    const int cc = tid >> 7;
    const int t7 = tid & 127;
    const int w  = t7 >> 5;
    const float2* __restrict__ pcs = &scs[cc * NP];
    float2 (*bufr)[128] = ex[cc];

    float vr[8], vi[8];
    #pragma unroll
    for (int m = 0; m < 8; ++m) { vr[m] = 0.f; vi[m] = 0.f; }
    if (t7 == 0) vr[0] = 1.0f;

    int idx = 0;

    #define UCOEF \
        float2 p1 = pcs[idx], p2 = pcs[idx+1], p3 = pcs[idx+2]; idx += 3; \
        float c1 = p1.x, s1 = p1.y, c2 = p2.x, s2 = p2.y, c3 = p3.x, s3 = p3.y; \
        float A00r =  c2*c1, A00i =  s2*s1; \
        float A01r = -s2*c1, A01i = -c2*s1; \
        float A10r =  s2*c1, A10i = -c2*s1; \
        float A11r =  c2*c1, A11i = -s2*s1; \
        float U00r = c3*A00r + s3*A00i, U00i = c3*A00i - s3*A00r; \
        float U01r = c3*A01r + s3*A01i, U01i = c3*A01i - s3*A01r; \
        float U10r = c3*A10r - s3*A10i, U10i = c3*A10i + s3*A10r; \
        float U11r = c3*A11r - s3*A11i, U11i = c3*A11i + s3*A11r;

    #define FUSED(B) { UCOEF \
        apply1q<B>(vr, vi, lane, U00r,U00i,U01r,U01i,U10r,U10i,U11r,U11i); }
    #define FUSEDW(WM) { UCOEF \
        apply1qW<WM>(vr, vi, cc, t7, w, bufr, U00r,U00i,U01r,U01i,U10r,U10i,U11r,U11i); }
    #define CRX(BC,BT) { float2 p = pcs[idx]; idx++; \
        applycrx<BC,BT>(vr, vi, lane, w, p.x, p.y); }
    #define CRXW(WM,ACT) { float2 p = pcs[idx]; idx++; \
        applycrxW<WM>(vr, vi, cc, t7, bufr, p.x, p.y, (ACT)); }

    // wire -> storage bit: 0:7 1:2 2:6 3:1 4:5 5:0 6:4 7:W8 8:3 9:W9
    #pragma unroll 1
    for (int layer = 0; layer < 2; ++layer) {
        FUSED(7) FUSED(2) FUSED(6) FUSED(1) FUSED(5)
        FUSED(0) FUSED(4) FUSEDW(1) FUSED(3) FUSEDW(2)
        // forward ring
        CRX(7,2) CRX(2,6) CRX(6,1) CRX(1,5) CRX(5,0) CRX(0,4)
        CRXW(1, (lane & 2) != 0)
        CRX(8,3)
        CRXW(2, (lane & 1) != 0)
        CRX(9,7)
        // backward ring
        CRX(9,3)
        CRXW(1, (lane & 1) != 0)
        CRX(8,4) CRX(4,0) CRX(0,5) CRX(5,1) CRX(1,6) CRX(6,2) CRX(2,7)
        CRXW(2, (lane & 16) != 0)
    }

    {
        float X, Y, Z;
        measureW<1>(vr, vi, cc, t7, w, bufr, X, Y, Z);       // wire 7 (bit 8)
        if (lane == 0) { mpart[cc][w][7] = X; mpart[cc][w][17] = Y; mpart[cc][w][27] = Z; }
    }
    {
        float X, Y, Z;
        measureW<2>(vr, vi, cc, t7, w, bufr, X, Y, Z);       // wire 9 (bit 9)
        if (lane == 0) { mpart[cc][w][9] = X; mpart[cc][w][19] = Y; mpart[cc][w][29] = Z; }
    }
    #define MEAS(v,B) { float X, Y, Z; measure<B>(vr, vi, lane, X, Y, Z); \
        if (lane == 0) { mpart[cc][w][v] = X; mpart[cc][w][10+(v)] = Y; mpart[cc][w][20+(v)] = Z; } }
    MEAS(0,7) MEAS(1,2) MEAS(2,6) MEAS(3,1) MEAS(4,5)
    MEAS(5,0) MEAS(6,4) MEAS(8,3)

    __syncthreads();
    if (tid < NOUT) {
        const int k = tid;
        float m1 = (mpart[0][0][k] + mpart[0][1][k]) + (mpart[0][2][k] + mpart[0][3][k]);
        float m2 = (mpart[1][0][k] + mpart[1][1][k]) + (mpart[1][2][k] + mpart[1][3][k]);
        float m3 = (mpart[2][0][k] + mpart[2][1][k]) + (mpart[2][2][k] + mpart[2][3][k]);
        float ar = ar_[0], ai = ai_[0];
        float brv = br_[0], bi = bi_[0];
        float gr = gr_[0], gi = gi_[0];
        float norm = sqrtf(ar*ar + ai*ai + brv*brv + bi*bi + gr*gr + gi*gi + 1e-9f);
        float re = (ar * m1 + brv * m2 + gr * m3) / norm;
        float im = (ai * m1 + bi * m2 + gi * m3) / norm;
        out[bt * NOUT + k] = sqrtf(re * re + im * im);
    }
}

extern "C" void kernel_launch(void* const* d_in, const int* in_sizes, int n_in,
                              void* d_out, int out_size)
{
    // d_in order: x, W1, b1, W2, b2, W3, b3, base1, base2, base3, ar, ai, br, bi, gr, gi
    qsb_params<<<3 * NP, 256>>>(
        (const float*)d_in[0],
        (const float*)d_in[1], (const float*)d_in[2], (const float*)d_in[7],
        (const float*)d_in[3], (const float*)d_in[4], (const float*)d_in[8],
        (const float*)d_in[5], (const float*)d_in[6], (const float*)d_in[9]);

    qsb_circuit<<<BATCH, 384>>>(
        (const float*)d_in[10], (const float*)d_in[11],
        (const float*)d_in[12], (const float*)d_in[13],
        (const float*)d_in[14], (const float*)d_in[15],
        (float*)d_out);
}

// round 12
// speedup vs baseline: 1.4959x; 1.0532x over previous
#include <cuda_runtime.h>
#include <math.h>

#define NP     100
#define BATCH  256
#define FD     256
#define NOUT   30

// precomputed (cos, sin) of half-angles: [batch][branch*100 + j]
__device__ float2       g_scs[BATCH][3 * NP];
__device__ float        g_m[3][BATCH][NOUT];
__device__ unsigned int g_cnt[BATCH];

// ---------------- kernel 1: param GEMM + sincos, 2 params per block ----------------
// grid 300: blockIdx = pair(150) * 2 + batch-half(2); 256 threads = 8 warps x 16 batches
__global__ void __launch_bounds__(256) qsb_params(
    const float* __restrict__ x,
    const float* __restrict__ W1, const float* __restrict__ b1, const float* __restrict__ base1,
    const float* __restrict__ W2, const float* __restrict__ b2, const float* __restrict__ base2,
    const float* __restrict__ W3, const float* __restrict__ b3, const float* __restrict__ base3)
{
    const int pp  = blockIdx.x >> 1;          // param pair 0..149
    const int h   = blockIdx.x & 1;           // batch half
    const int jj0 = pp * 2;                   // global param idx (never straddles branch)
    const int br  = jj0 / NP;
    const int j0  = jj0 - br * NP;
    const float* __restrict__ W  = (br == 0) ? W1 : (br == 1) ? W2 : W3;
    const float* __restrict__ bb = (br == 0) ? b1 : (br == 1) ? b2 : b3;
    const float* __restrict__ bs = (br == 0) ? base1 : (br == 1) ? base2 : base3;

    const int lane = threadIdx.x & 31;
    const int wid  = threadIdx.x >> 5;        // 0..7

    const float4* __restrict__ w40 = (const float4*)(W + j0 * FD);
    const float4* __restrict__ w41 = (const float4*)(W + (j0 + 1) * FD);
    const float4 wa0 = w40[lane], wb0 = w40[lane + 32];
    const float4 wa1 = w41[lane], wb1 = w41[lane + 32];
    const float bias0 = bb[j0] + bs[j0];
    const float bias1 = bb[j0 + 1] + bs[j0 + 1];

    #pragma unroll 2
    for (int t = 0; t < 16; ++t) {
        const int bt = h * 128 + wid * 16 + t;
        const float4* __restrict__ x4 = (const float4*)(x + bt * FD);
        float4 xa = x4[lane];
        float4 xb = x4[lane + 32];
        float s0 = wa0.x*xa.x + wa0.y*xa.y + wa0.z*xa.z + wa0.w*xa.w
                 + wb0.x*xb.x + wb0.y*xb.y + wb0.z*xb.z + wb0.w*xb.w;
        float s1 = wa1.x*xa.x + wa1.y*xa.y + wa1.z*xa.z + wa1.w*xa.w
                 + wb1.x*xb.x + wb1.y*xb.y + wb1.z*xb.z + wb1.w*xb.w;
        #pragma unroll
        for (int o = 16; o; o >>= 1) {
            s0 += __shfl_xor_sync(0xffffffffu, s0, o);
            s1 += __shfl_xor_sync(0xffffffffu, s1, o);
        }
        if (lane == 0) {
            float h0 = 3.14159265358979f / (1.0f + __expf(-(s0 + bias0)));
            float h1 = 3.14159265358979f / (1.0f + __expf(-(s1 + bias1)));
            float c0, n0, c1, n1;
            __sincosf(h0, &n0, &c0);
            __sincosf(h1, &n1, &c1);
            g_scs[bt][jj0]     = make_float2(c0, n0);
            g_scs[bt][jj0 + 1] = make_float2(c1, n1);
        }
    }
}

// ---------------- circuit machinery ----------------
// Storage map (wire -> storage bit): regs bits 0..2, lanes 3..7, warps 8..9
//  wire: 0   1   2   3   4   5   6   7   8   9
//  bit : 7   2   6   1   5   0   4   8   3   9

__device__ __forceinline__ float wred(float v) {
    #pragma unroll
    for (int o = 16; o; o >>= 1) v += __shfl_xor_sync(0xffffffffu, v, o);
    return v;
}

template<int B>
__device__ __forceinline__ void apply1q(float* vr, float* vi, int lane,
    float U00r, float U00i, float U01r, float U01i,
    float U10r, float U10i, float U11r, float U11i)
{
    if constexpr (B < 3) {
        constexpr int st = 1 << B;
        #pragma unroll
        for (int q = 0; q < 4; ++q) {
            const int m0 = ((q >> B) << (B + 1)) | (q & (st - 1));
            const int m1 = m0 | st;
            float a0r = vr[m0], a0i = vi[m0], a1r = vr[m1], a1i = vi[m1];
            vr[m0] = U00r*a0r - U00i*a0i + U01r*a1r - U01i*a1i;
            vi[m0] = U00r*a0i + U00i*a0r + U01r*a1i + U01i*a1r;
            vr[m1] = U10r*a0r - U10i*a0i + U11r*a1r - U11i*a1i;
            vi[m1] = U10r*a0i + U10i*a0r + U11r*a1i + U11i*a1r;
        }
    } else {
        constexpr int lm = 1 << (B - 3);
        const bool r = (lane & lm) != 0;
        float cmr = r ? U11r : U00r, cmi = r ? U11i : U00i;
        float cpr = r ? U10r : U01r, cpi = r ? U10i : U01i;
        #pragma unroll
        for (int m = 0; m < 8; ++m) {
            float pr = __shfl_xor_sync(0xffffffffu, vr[m], lm);
            float pi = __shfl_xor_sync(0xffffffffu, vi[m], lm);
            float mr = vr[m], mi = vi[m];
            vr[m] = cmr*mr - cmi*mi + cpr*pr - cpi*pi;
            vi[m] = cmr*mi + cmi*mr + cpr*pi + cpi*pr;
        }
    }
}

template<int WM>
__device__ __forceinline__ void apply1qW(float* vr, float* vi, int t7, int w,
    float2 (*ex)[128],
    float U00r, float U00i, float U01r, float U01i,
    float U10r, float U10i, float U11r, float U11i)
{
    const bool hi = (w & WM) != 0;
    float cmr = hi ? U11r : U00r, cmi = hi ? U11i : U00i;
    float cpr = hi ? U10r : U01r, cpi = hi ? U10i : U01i;
    __syncthreads();
    #pragma unroll
    for (int m = 0; m < 8; ++m) ex[m][t7] = make_float2(vr[m], vi[m]);
    __syncthreads();
    const int p = t7 ^ (WM << 5);
    #pragma unroll
    for (int m = 0; m < 8; ++m) {
        float2 pv = ex[m][p];
        float mr = vr[m], mi = vi[m];
        vr[m] = cmr*mr - cmi*mi + cpr*pv.x - cpi*pv.y;
        vi[m] = cmr*mi + cmi*mr + cpr*pv.y + cpi*pv.x;
    }
}

template<int BC, int BT>
__device__ __forceinline__ void applycrx(float* vr, float* vi, int lane, int w, float cg, float sg)
{
    bool act = true;
    if constexpr (BC >= 8)      act = (w & (1 << (BC - 8))) != 0;
    else if constexpr (BC >= 3) act = (lane & (1 << (BC - 3))) != 0;

    if constexpr (BT < 3) {
        constexpr int tm = 1 << BT;
        if constexpr (BC < 3) {
            #pragma unroll
            for (int m0 = 0; m0 < 8; ++m0)
                if ((m0 & (1 << BC)) && !(m0 & tm)) {
                    const int m1 = m0 | tm;
                    float a0r = vr[m0], a0i = vi[m0], a1r = vr[m1], a1i = vi[m1];
                    vr[m0] = cg*a0r + sg*a1i; vi[m0] = cg*a0i - sg*a1r;
                    vr[m1] = cg*a1r + sg*a0i; vi[m1] = cg*a1i - sg*a0r;
                }
        } else {
            if (act) {
                #pragma unroll
                for (int q = 0; q < 4; ++q) {
                    const int m0 = ((q >> BT) << (BT + 1)) | (q & (tm - 1));
                    const int m1 = m0 | tm;
                    float a0r = vr[m0], a0i = vi[m0], a1r = vr[m1], a1i = vi[m1];
                    vr[m0] = cg*a0r + sg*a1i; vi[m0] = cg*a0i - sg*a1r;
                    vr[m1] = cg*a1r + sg*a0i; vi[m1] = cg*a1i - sg*a0r;
                }
            }
        }
    } else {
        constexpr int lm = 1 << (BT - 3);
        if constexpr (BC < 3) {
            #pragma unroll
            for (int m = 0; m < 8; ++m)
                if (m & (1 << BC)) {
                    float pr = __shfl_xor_sync(0xffffffffu, vr[m], lm);
                    float pi = __shfl_xor_sync(0xffffffffu, vi[m], lm);
                    float mr = vr[m], mi = vi[m];
                    vr[m] = cg*mr + sg*pi; vi[m] = cg*mi - sg*pr;
                }
        } else if constexpr (BC >= 8) {
            if (act) {
                #pragma unroll
                for (int m = 0; m < 8; ++m) {
                    float pr = __shfl_xor_sync(0xffffffffu, vr[m], lm);
                    float pi = __shfl_xor_sync(0xffffffffu, vi[m], lm);
                    float mr = vr[m], mi = vi[m];
                    vr[m] = cg*mr + sg*pi; vi[m] = cg*mi - sg*pr;
                }
            }
        } else {
            #pragma unroll
            for (int m = 0; m < 8; ++m) {
                float pr = __shfl_xor_sync(0xffffffffu, vr[m], lm);
                float pi = __shfl_xor_sync(0xffffffffu, vi[m], lm);
                float mr = vr[m], mi = vi[m];
                float nr = cg*mr + sg*pi, ni = cg*mi - sg*pr;
                vr[m] = act ? nr : mr; vi[m] = act ? ni : mi;
            }
        }
    }
}

template<int WM>
__device__ __forceinline__ void applycrxW(float* vr, float* vi, int t7,
    float2 (*ex)[128], float cg, float sg, bool act)
{
    __syncthreads();
    if (act) {
        #pragma unroll
        for (int m = 0; m < 8; ++m) ex[m][t7] = make_float2(vr[m], vi[m]);
    }
    __syncthreads();
    if (act) {
        const int p = t7 ^ (WM << 5);
        #pragma unroll
        for (int m = 0; m < 8; ++m) {
            float2 pv = ex[m][p];
            float mr = vr[m], mi = vi[m];
            vr[m] = cg*mr + sg*pv.y; vi[m] = cg*mi - sg*pv.x;
        }
    }
}

template<int B>
__device__ __forceinline__ void measure(const float* vr, const float* vi, int lane,
                                        float& X, float& Y, float& Z)
{
    float zr = 0.f, zi = 0.f, zd = 0.f;
    if constexpr (B < 3) {
        constexpr int st = 1 << B;
        #pragma unroll
        for (int q = 0; q < 4; ++q) {
            const int m0 = ((q >> B) << (B + 1)) | (q & (st - 1));
            const int m1 = m0 | st;
            zr += vr[m0]*vr[m1] + vi[m0]*vi[m1];
            zi += vr[m0]*vi[m1] - vi[m0]*vr[m1];
            zd += vr[m0]*vr[m0] + vi[m0]*vi[m0] - vr[m1]*vr[m1] - vi[m1]*vi[m1];
        }
        X = 2.f * wred(zr); Y = 2.f * wred(zi); Z = wred(zd);
    } else {
        constexpr int lm = 1 << (B - 3);
        const float sgn = (lane & lm) ? -1.f : 1.f;
        #pragma unroll
        for (int m = 0; m < 8; ++m) {
            float pr = __shfl_xor_sync(0xffffffffu, vr[m], lm);
            float pi = __shfl_xor_sync(0xffffffffu, vi[m], lm);
            float mr = vr[m], mi = vi[m];
            zr += mr*pr + mi*pi;
            zi += mr*pi - mi*pr;
            zd += mr*mr + mi*mi;
        }
        X = wred(zr); Y = wred(zi * sgn); Z = wred(zd * sgn);
    }
}

template<int WM>
__device__ __forceinline__ void measureW(const float* vr, const float* vi, int t7, int w,
    float2 (*ex)[128], float& X, float& Y, float& Z)
{
    __syncthreads();
    #pragma unroll
    for (int m = 0; m < 8; ++m) ex[m][t7] = make_float2(vr[m], vi[m]);
    __syncthreads();
    const int p = t7 ^ (WM << 5);
    const float sgn = (w & WM) ? -1.f : 1.f;
    float zr = 0.f, zi = 0.f, zd = 0.f;
    #pragma unroll
    for (int m = 0; m < 8; ++m) {
        float2 pv = ex[m][p];
        float mr = vr[m], mi = vi[m];
        zr += mr*pv.x + mi*pv.y;
        zi += mr*pv.y - mi*pv.x;
        zd += mr*mr + mi*mi;
    }
    X = wred(zr); Y = wred(zi * sgn); Z = wred(zd * sgn);
}

// ---------------- kernel 2: one circuit per block (grid 768, 128 threads) ----------------
__global__ void __launch_bounds__(128) qsb_circuit(
    const float* __restrict__ ar_, const float* __restrict__ ai_,
    const float* __restrict__ br_, const float* __restrict__ bi_,
    const float* __restrict__ gr_, const float* __restrict__ gi_,
    float* __restrict__ out)
{
    const int bt   = blockIdx.x & 255;
    const int br   = blockIdx.x >> 8;
    const int t7   = threadIdx.x;
    const int lane = t7 & 31;
    const int w    = t7 >> 5;

    __shared__ float2 scs[NP];
    __shared__ float2 ex[8][128];
    __shared__ float  mpart[4][NOUT];
    __shared__ int    sIsLast;

    if (t7 < NP) scs[t7] = g_scs[bt][br * NP + t7];
    __syncthreads();

    float vr[8], vi[8];
    #pragma unroll
    for (int m = 0; m < 8; ++m) { vr[m] = 0.f; vi[m] = 0.f; }
    if (t7 == 0) vr[0] = 1.0f;

    int idx = 0;

    #define UCOEF \
        float2 p1 = scs[idx], p2 = scs[idx+1], p3 = scs[idx+2]; idx += 3; \
        float c1 = p1.x, s1 = p1.y, c2 = p2.x, s2 = p2.y, c3 = p3.x, s3 = p3.y; \
        float A00r =  c2*c1, A00i =  s2*s1; \
        float A01r = -s2*c1, A01i = -c2*s1; \
        float A10r =  s2*c1, A10i = -c2*s1; \
        float A11r =  c2*c1, A11i = -s2*s1; \
        float U00r = c3*A00r + s3*A00i, U00i = c3*A00i - s3*A00r; \
        float U01r = c3*A01r + s3*A01i, U01i = c3*A01i - s3*A01r; \
        float U10r = c3*A10r - s3*A10i, U10i = c3*A10i + s3*A10r; \
        float U11r = c3*A11r - s3*A11i, U11i = c3*A11i + s3*A11r;

    #define FUSED(B) { UCOEF \
        apply1q<B>(vr, vi, lane, U00r,U00i,U01r,U01i,U10r,U10i,U11r,U11i); }
    #define FUSEDW(WM) { UCOEF \
        apply1qW<WM>(vr, vi, t7, w, ex, U00r,U00i,U01r,U01i,U10r,U10i,U11r,U11i); }
    #define CRX(BC,BT) { float2 p = scs[idx]; idx++; \
        applycrx<BC,BT>(vr, vi, lane, w, p.x, p.y); }
    #define CRXW(WM,ACT) { float2 p = scs[idx]; idx++; \
        applycrxW<WM>(vr, vi, t7, ex, p.x, p.y, (ACT)); }

    // wire -> storage bit: 0:7 1:2 2:6 3:1 4:5 5:0 6:4 7:W8 8:3 9:W9
    #pragma unroll 1
    for (int layer = 0; layer < 2; ++layer) {
        FUSED(7) FUSED(2) FUSED(6) FUSED(1) FUSED(5)
        FUSED(0) FUSED(4) FUSEDW(1) FUSED(3) FUSEDW(2)
        // forward ring
        CRX(7,2) CRX(2,6) CRX(6,1) CRX(1,5) CRX(5,0) CRX(0,4)
        CRXW(1, (lane & 2) != 0)
        CRX(8,3)
        CRXW(2, (lane & 1) != 0)
        CRX(9,7)
        // backward ring
        CRX(9,3)
        CRXW(1, (lane & 1) != 0)
        CRX(8,4) CRX(4,0) CRX(0,5) CRX(5,1) CRX(1,6) CRX(6,2) CRX(2,7)
        CRXW(2, (lane & 16) != 0)
    }

    {
        float X, Y, Z;
        measureW<1>(vr, vi, t7, w, ex, X, Y, Z);             // wire 7 (bit 8)
        if (lane == 0) { mpart[w][7] = X; mpart[w][17] = Y; mpart[w][27] = Z; }
    }
    {
        float X, Y, Z;
        measureW<2>(vr, vi, t7, w, ex, X, Y, Z);             // wire 9 (bit 9)
        if (lane == 0) { mpart[w][9] = X; mpart[w][19] = Y; mpart[w][29] = Z; }
    }
    #define MEAS(v,B) { float X, Y, Z; measure<B>(vr, vi, lane, X, Y, Z); \
        if (lane == 0) { mpart[w][v] = X; mpart[w][10+(v)] = Y; mpart[w][20+(v)] = Z; } }
    MEAS(0,7) MEAS(1,2) MEAS(2,6) MEAS(3,1) MEAS(4,5)
    MEAS(5,0) MEAS(6,4) MEAS(8,3)
    __syncthreads();

    // publish per-branch expvals; last block for this bt does the combine
    if (t7 < NOUT) {
        float s = (mpart[0][t7] + mpart[1][t7]) + (mpart[2][t7] + mpart[3][t7]);
        g_m[br][bt][t7] = s;
        __threadfence();
    }
    __syncthreads();
    if (t7 == 0) {
        unsigned int old = atomicAdd(&g_cnt[bt], 1u);
        sIsLast = (old == 2u);
    }
    __syncthreads();
    if (sIsLast) {
        if (t7 < NOUT) {
            __threadfence();
            float m1 = g_m[0][bt][t7];
            float m2 = g_m[1][bt][t7];
            float m3 = g_m[2][bt][t7];
            float ar = ar_[0], ai = ai_[0];
            float brv = br_[0], bi = bi_[0];
            float gr = gr_[0], gi = gi_[0];
            float norm = sqrtf(ar*ar + ai*ai + brv*brv + bi*bi + gr*gr + gi*gi + 1e-9f);
            float re = (ar * m1 + brv * m2 + gr * m3) / norm;
            float im = (ai * m1 + bi * m2 + gi * m3) / norm;
            out[bt * NOUT + t7] = sqrtf(re * re + im * im);
        }
        if (t7 == 0) g_cnt[bt] = 0u;   // reset for next graph replay
    }
}

extern "C" void kernel_launch(void* const* d_in, const int* in_sizes, int n_in,
                              void* d_out, int out_size)
{
    // d_in order: x, W1, b1, W2, b2, W3, b3, base1, base2, base3, ar, ai, br, bi, gr, gi
    qsb_params<<<2 * 150, 256>>>(
        (const float*)d_in[0],
        (const float*)d_in[1], (const float*)d_in[2], (const float*)d_in[7],
        (const float*)d_in[3], (const float*)d_in[4], (const float*)d_in[8],
        (const float*)d_in[5], (const float*)d_in[6], (const float*)d_in[9]);

    qsb_circuit<<<3 * BATCH, 128>>>(
        (const float*)d_in[10], (const float*)d_in[11],
        (const float*)d_in[12], (const float*)d_in[13],
        (const float*)d_in[14], (const float*)d_in[15],
        (float*)d_out);
}